// round 11
// baseline (speedup 1.0000x reference)
#include <cuda_runtime.h>
#include <cuda_fp16.h>
#include <cstdint>

typedef uint32_t u32;

#define CHUNKSZ 512
#define NCHUNK  8
#define HH      1024
#define FF      4096
#define MROWS   2048          /* rows per chunk (B*CHUNKSZ) */
#define MALL    16384         /* all rows (B*S) */
#define NOUT    16777216

// ---- scratch (device globals; no allocations allowed) ----
__device__ __half g_xh [(size_t)NOUT];         // fp16 x (32MB)
__device__ __half g_u0h[(size_t)MALL * FF];    // u0 all chunks (128MB)
__device__ __half g_u2h[(size_t)MALL * FF];    // u2 all chunks (128MB)
__device__ __half g_vh [(size_t)MROWS * FF];   // v, chunk-local (16MB)
__device__ __half g_w0T[(size_t)FF * HH];      // w0^T [n=4096][k=1024]
__device__ __half g_w2T[(size_t)FF * HH];
__device__ __half g_w1T[(size_t)HH * FF];      // w1^T [n=1024][k=4096]
__device__ float g_partial[256];
__device__ unsigned int g_count;
__device__ float g_D;
__device__ float g_total;

// =================== helpers ===================
__device__ __forceinline__ u32 smem_u32(const void* p) {
    u32 a; asm("{ .reg .u64 t; cvta.to.shared.u64 t, %1; cvt.u32.u64 %0, t; }" : "=r"(a) : "l"(p));
    return a;
}

#define CP16(dst, src) \
    asm volatile("cp.async.cg.shared.global [%0], [%1], 16;" :: "r"(dst), "l"(src) : "memory")
#define CPCOMMIT() asm volatile("cp.async.commit_group;" ::: "memory")
#define CPWAIT1()  asm volatile("cp.async.wait_group 1;" ::: "memory")
#define CPWAIT2()  asm volatile("cp.async.wait_group 2;" ::: "memory")

#define LDSM4(r, addr) \
    asm volatile("ldmatrix.sync.aligned.m8n8.x4.shared.b16 {%0,%1,%2,%3}, [%4];" \
        : "=r"((r)[0]), "=r"((r)[1]), "=r"((r)[2]), "=r"((r)[3]) : "r"(addr))

#define MMA16(d, a, b0_, b1_) \
    asm volatile("mma.sync.aligned.m16n8k16.row.col.f32.f16.f16.f32 " \
        "{%0,%1,%2,%3}, {%4,%5,%6,%7}, {%8,%9}, {%0,%1,%2,%3};" \
        : "+f"((d)[0]), "+f"((d)[1]), "+f"((d)[2]), "+f"((d)[3]) \
        : "r"((a)[0]), "r"((a)[1]), "r"((a)[2]), "r"((a)[3]), "r"(b0_), "r"(b1_))

// rows x 64 k-halves (128B data), row stride 144B -> conflict-free LDSM/STS
#define ROWSTRB  144
#define TILE128  18432   /* 128*144 */
#define TILE64   9216    /*  64*144 */
#define MROWB    2304    /*  16*144 */

// =================== small kernels ===================
__global__ void conv_x_kernel(const float* __restrict__ x) {
    int i = (blockIdx.x * 256 + threadIdx.x) * 4;
    float4 v = *(const float4*)(x + i);
    *(__half2*)(g_xh + i)     = __floats2half2_rn(v.x, v.y);
    *(__half2*)(g_xh + i + 2) = __floats2half2_rn(v.z, v.w);
    if (blockIdx.x == 0 && threadIdx.x == 0) { g_D = 1.0f; g_total = 0.0f; g_count = 0u; }
}

// 3 transposes in one launch (z selects weight); out[C][R] = half(in[R][C])
__global__ void transpose_all(const float* __restrict__ w0, const float* __restrict__ w1,
                              const float* __restrict__ w2) {
    __shared__ float t[32][33];
    int z = blockIdx.z;
    const float* in; __half* out; int R, C, c0, r0;
    if (z == 0)      { in = w0; out = g_w0T; R = HH; C = FF; c0 = blockIdx.x * 32; r0 = blockIdx.y * 32; }
    else if (z == 1) { in = w2; out = g_w2T; R = HH; C = FF; c0 = blockIdx.x * 32; r0 = blockIdx.y * 32; }
    else             { in = w1; out = g_w1T; R = FF; C = HH; c0 = blockIdx.y * 32; r0 = blockIdx.x * 32; }
    #pragma unroll
    for (int i = 0; i < 32; i += 8)
        t[threadIdx.y + i][threadIdx.x] = in[(size_t)(r0 + threadIdx.y + i) * C + c0 + threadIdx.x];
    __syncthreads();
    #pragma unroll
    for (int i = 0; i < 32; i += 8)
        out[(size_t)(c0 + threadIdx.y + i) * R + r0 + threadIdx.x] = __float2half_rn(t[threadIdx.x][threadIdx.y + i]);
}

// vh[row_local] = silu(D*u0[grow]) * u2[grow], 8 halves/thread
__global__ void silu_mul_kernel(int chunk) {
    const float D = g_D;
    size_t idx = ((size_t)blockIdx.x * 256 + threadIdx.x) * 8;
    int rl  = (int)(idx >> 12);
    int col = (int)(idx & 4095);
    int grow = ((rl >> 9) << 12) + chunk * CHUNKSZ + (rl & 511);
    size_t gi = (size_t)grow * FF + col;
    uint4 a4 = *(const uint4*)(g_u0h + gi);
    uint4 b4 = *(const uint4*)(g_u2h + gi);
    const __half2* a = (const __half2*)&a4;
    const __half2* b = (const __half2*)&b4;
    uint4 o4;
    __half2* o = (__half2*)&o4;
    #pragma unroll
    for (int j = 0; j < 4; j++) {
        float2 af = __half22float2(a[j]);
        float2 bf = __half22float2(b[j]);
        float z0 = D * af.x, z1 = D * af.y;
        float s0 = z0 / (1.0f + __expf(-z0)), s1 = z1 / (1.0f + __expf(-z1));
        o[j] = __floats2half2_rn(s0 * bf.x, s1 * bf.y);
    }
    *(uint4*)(g_vh + (size_t)rl * FF + col) = o4;
}

// =================== GEMM1 (mega): u{0,2}[all rows] = x @ w{0,2}T ===================
// CTA 128x128, 256 thr (8 warps 4m x 2n, warp 32x64), M=16384, K=1024, k-tile 64, 3 stages, occ 2.
#define ST1_STAGE (2 * TILE128)    /* 36864 */
#define ST1_BYTES (3 * ST1_STAGE)  /* 110592 */

__device__ __forceinline__ void g1_load(u32 base, const __half* wT, int tid,
                                        int m0, int n0, int kt) {
    #pragma unroll
    for (int i = 0; i < 4; i++) {
        int idx = tid + i * 256;
        int row = idx >> 3, kq = idx & 7;
        CP16(base + (u32)(row * ROWSTRB + kq * 16),
             g_xh + (size_t)(m0 + row) * HH + kt * 64 + kq * 8);
    }
    #pragma unroll
    for (int i = 0; i < 4; i++) {
        int idx = tid + i * 256;
        int row = idx >> 3, kq = idx & 7;
        CP16(base + TILE128 + (u32)(row * ROWSTRB + kq * 16),
             wT + (size_t)(n0 + row) * HH + kt * 64 + kq * 8);
    }
}

__global__ __launch_bounds__(256, 2)
void gemm1_tc()
{
    extern __shared__ float smem[];
    const u32 sb = smem_u32(smem);
    const int tid = threadIdx.x, lane = tid & 31, wid = tid >> 5;
    const int wm = wid & 3, wn = wid >> 2;            // 4m x 2n warps, tile 32x64
    const int m0 = blockIdx.y * 128, n0 = blockIdx.x * 128;
    const int z = blockIdx.z;
    const __half* wT = z ? g_w2T : g_w0T;
    __half* uout = z ? g_u2h : g_u0h;

    float acc[2][8][4];
    #pragma unroll
    for (int a = 0; a < 2; a++)
        #pragma unroll
        for (int b = 0; b < 8; b++)
            #pragma unroll
            for (int c = 0; c < 4; c++) acc[a][b][c] = 0.f;

    const u32 aoff = (u32)((wm * 32 + (lane & 15)) * ROWSTRB) + ((lane >> 4) & 1) * 16;
    const u32 boff = (u32)((wn * 64 + (lane & 15)) * ROWSTRB) + ((lane >> 4) & 1) * 16;

    g1_load(sb, wT, tid, m0, n0, 0); CPCOMMIT();
    g1_load(sb + ST1_STAGE, wT, tid, m0, n0, 1); CPCOMMIT();

    const int KT = HH / 64;  // 16
    for (int kt = 0; kt < KT; ++kt) {
        const u32 base = sb + (u32)(kt % 3) * ST1_STAGE;
        CPWAIT1();
        __syncthreads();
        if (kt + 2 < KT) g1_load(sb + (u32)((kt + 2) % 3) * ST1_STAGE, wT, tid, m0, n0, kt + 2);
        CPCOMMIT();
        #pragma unroll
        for (int ks = 0; ks < 4; ++ks) {
            u32 A[2][4];
            LDSM4(A[0], base + aoff + 0 * MROWB + ks * 32);
            LDSM4(A[1], base + aoff + 1 * MROWB + ks * 32);
            #pragma unroll
            for (int tp = 0; tp < 4; ++tp) {
                u32 b[4];
                LDSM4(b, base + TILE128 + boff + tp * MROWB + ks * 32);
                #pragma unroll
                for (int mt = 0; mt < 2; ++mt) {
                    MMA16(acc[mt][2 * tp],     A[mt], b[0], b[2]);
                    MMA16(acc[mt][2 * tp + 1], A[mt], b[1], b[3]);
                }
            }
        }
    }

    // epilogue: store u as fp16 (global row index)
    const int gq = lane >> 2, tg = lane & 3;
    #pragma unroll
    for (int mt = 0; mt < 2; ++mt) {
        #pragma unroll
        for (int nt = 0; nt < 8; ++nt) {
            const int col = n0 + wn * 64 + nt * 8 + tg * 2;
            #pragma unroll
            for (int h = 0; h < 2; ++h) {
                const int row = m0 + wm * 32 + mt * 16 + gq + h * 8;
                *(__half2*)&uout[(size_t)row * FF + col] =
                    __floats2half2_rn(acc[mt][nt][h * 2], acc[mt][nt][h * 2 + 1]);
            }
        }
    }
}

// =================== GEMM2: out = D^2 * (v @ w1T) + loss + D-update ===================
// CTA 64x128, 256 thr: 8 warps = 2k x 2m x 2n (split-K), warp tile 32x64.
// K=4096, k-tile 64 (each k-warp does 2 of 4 k16 steps), 4 stages, occ 2.
// Last CTA (atomic counter) reduces g_partial deterministically and updates D.
#define ST2_STAGE (TILE64 + TILE128)  /* 27648 */
#define ST2_BYTES (4 * ST2_STAGE)     /* 110592 */

__device__ __forceinline__ void g2_load(u32 base, int tid, int m0, int n0, int kt) {
    #pragma unroll
    for (int i = 0; i < 2; i++) {
        int idx = tid + i * 256;
        int row = idx >> 3, kq = idx & 7;
        CP16(base + (u32)(row * ROWSTRB + kq * 16),
             g_vh + (size_t)(m0 + row) * FF + kt * 64 + kq * 8);
    }
    #pragma unroll
    for (int i = 0; i < 4; i++) {
        int idx = tid + i * 256;
        int row = idx >> 3, kq = idx & 7;
        CP16(base + TILE64 + (u32)(row * ROWSTRB + kq * 16),
             g_w1T + (size_t)(n0 + row) * FF + kt * 64 + kq * 8);
    }
}

__global__ __launch_bounds__(256, 2)
void gemm2_tc(const float* __restrict__ x, float* __restrict__ outp, int chunk)
{
    extern __shared__ float smem[];
    const u32 sb = smem_u32(smem);
    const int tid = threadIdx.x, lane = tid & 31, wid = tid >> 5;
    const int wk = wid & 1, pair = wid >> 1;          // pair in 0..3 encodes (wm, wn)
    const int wm = pair & 1, wn = pair >> 1;
    const int m0 = blockIdx.y * 64, n0 = blockIdx.x * 128;

    float acc[2][8][4];
    #pragma unroll
    for (int a = 0; a < 2; a++)
        #pragma unroll
        for (int b = 0; b < 8; b++)
            #pragma unroll
            for (int c = 0; c < 4; c++) acc[a][b][c] = 0.f;

    const u32 aoff = (u32)((wm * 32 + (lane & 15)) * ROWSTRB) + ((lane >> 4) & 1) * 16;
    const u32 boff = (u32)((wn * 64 + (lane & 15)) * ROWSTRB) + ((lane >> 4) & 1) * 16;

    g2_load(sb, tid, m0, n0, 0); CPCOMMIT();
    g2_load(sb + ST2_STAGE, tid, m0, n0, 1); CPCOMMIT();
    g2_load(sb + 2 * ST2_STAGE, tid, m0, n0, 2); CPCOMMIT();

    const int KT = FF / 64;  // 64
    for (int kt = 0; kt < KT; ++kt) {
        const u32 base = sb + (u32)(kt & 3) * ST2_STAGE;
        CPWAIT2();
        __syncthreads();
        if (kt + 3 < KT) g2_load(sb + (u32)((kt + 3) & 3) * ST2_STAGE, tid, m0, n0, kt + 3);
        CPCOMMIT();
        #pragma unroll
        for (int kss = 0; kss < 2; ++kss) {      // this warp's half of the 4 k16 steps
            const int ks = wk * 2 + kss;
            u32 A[2][4];
            LDSM4(A[0], base + aoff + 0 * MROWB + ks * 32);
            LDSM4(A[1], base + aoff + 1 * MROWB + ks * 32);
            #pragma unroll
            for (int tp = 0; tp < 4; ++tp) {
                u32 b[4];
                LDSM4(b, base + TILE64 + boff + tp * MROWB + ks * 32);
                #pragma unroll
                for (int mt = 0; mt < 2; ++mt) {
                    MMA16(acc[mt][2 * tp],     A[mt], b[0], b[2]);
                    MMA16(acc[mt][2 * tp + 1], A[mt], b[1], b[3]);
                }
            }
        }
    }

    // fold wk=1 accumulators into wk=0 via smem (32KB, reusing stage memory)
    __syncthreads();
    float* accbuf = smem;
    const int slot = pair * 32 + lane;           // 0..127
    if (wk == 1) {
        float* dst = accbuf + (size_t)slot * 64;
        #pragma unroll
        for (int mt = 0; mt < 2; ++mt)
            #pragma unroll
            for (int nt = 0; nt < 8; ++nt)
                #pragma unroll
                for (int c = 0; c < 4; ++c)
                    dst[mt * 32 + nt * 4 + c] = acc[mt][nt][c];
    }
    __syncthreads();

    // epilogue (wk=0 warps only): out = D^2*(acc0+acc1), fused (out-x)^2 partial
    const float D = g_D, D2 = D * D;
    const int gq = lane >> 2, tg = lane & 3;
    float sq = 0.0f;
    if (wk == 0) {
        const float* src = accbuf + (size_t)slot * 64;
        #pragma unroll
        for (int mt = 0; mt < 2; ++mt) {
            #pragma unroll
            for (int nt = 0; nt < 8; ++nt) {
                const int col = n0 + wn * 64 + nt * 8 + tg * 2;
                #pragma unroll
                for (int h = 0; h < 2; ++h) {
                    const int lm = m0 + wm * 32 + mt * 16 + gq + h * 8;
                    const int g = ((lm >> 9) << 12) + chunk * CHUNKSZ + (lm & 511);
                    float2 xv = *(const float2*)(x + (size_t)g * HH + col);
                    float2 ov;
                    ov.x = D2 * (acc[mt][nt][h * 2]     + src[mt * 32 + nt * 4 + h * 2]);
                    ov.y = D2 * (acc[mt][nt][h * 2 + 1] + src[mt * 32 + nt * 4 + h * 2 + 1]);
                    *(float2*)(outp + (size_t)g * HH + col) = ov;
                    float d0 = ov.x - xv.x, d1 = ov.y - xv.y;
                    sq += d0 * d0 + d1 * d1;
                }
            }
        }
    }
    #pragma unroll
    for (int off = 16; off > 0; off >>= 1)
        sq += __shfl_xor_sync(0xFFFFFFFFu, sq, off);
    __syncthreads();
    float* red = accbuf + 8192;
    if (lane == 0) red[wid] = sq;
    __syncthreads();

    __shared__ unsigned int s_last;
    if (tid == 0) {
        float s = 0.f;
        #pragma unroll
        for (int i = 0; i < 8; i++) s += red[i];
        g_partial[blockIdx.y * gridDim.x + blockIdx.x] = s;
        __threadfence();
        unsigned int old = atomicAdd(&g_count, 1u);
        s_last = (old == 255u) ? 1u : 0u;
    }
    __syncthreads();
    if (s_last) {
        // deterministic final reduce over fixed-order g_partial[0..255]
        red = accbuf;                      // reuse smem
        red[tid] = g_partial[tid];
        __syncthreads();
        for (int s2 = 128; s2 > 0; s2 >>= 1) {
            if (tid < s2) red[tid] += red[tid + s2];
            __syncthreads();
        }
        if (tid == 0) {
            float loss = red[0] * (1.0f / (float)(MROWS * HH));
            float tot = g_total + loss;
            g_total = tot;
            g_D = g_D * (1.0f - 0.001f * loss);
            g_count = 0u;
            if (chunk == NCHUNK - 1) outp[NOUT] = tot * (1.0f / (float)NCHUNK);
        }
    }
}

// =================== host ===================
extern "C" void kernel_launch(void* const* d_in, const int* in_sizes, int n_in,
                              void* d_out, int out_size)
{
    const float* x  = (const float*)d_in[0];
    const float* w0 = (const float*)d_in[1];
    const float* w1 = (const float*)d_in[2];
    const float* w2 = (const float*)d_in[3];
    float* out = (float*)d_out;

    cudaFuncSetAttribute(gemm1_tc, cudaFuncAttributeMaxDynamicSharedMemorySize, ST1_BYTES);
    cudaFuncSetAttribute(gemm2_tc, cudaFuncAttributeMaxDynamicSharedMemorySize, ST2_BYTES);

    conv_x_kernel<<<NOUT / 1024, 256>>>(x);
    transpose_all<<<dim3(128, 32, 3), dim3(32, 8)>>>(w0, w1, w2);

    // All chunks' u0/u2 in ONE mega-GEMM (chunk-independent: no D involved)
    gemm1_tc<<<dim3(32, MALL / 128, 2), 256, ST1_BYTES>>>();

    // Sequential D-recurrence chain (loss reduce + D update fused into gemm2)
    for (int c = 0; c < NCHUNK; ++c) {
        silu_mul_kernel<<<(MROWS * FF) / 2048, 256>>>(c);
        gemm2_tc<<<dim3(8, 32), 256, ST2_BYTES>>>(x, out, c);
    }
}

// round 12
// speedup vs baseline: 1.0966x; 1.0966x over previous
#include <cuda_runtime.h>
#include <cuda_fp16.h>
#include <cstdint>

typedef uint32_t u32;

#define CHUNKSZ 512
#define NCHUNK  8
#define HH      1024
#define FF      4096
#define MROWS   2048          /* rows per chunk (B*CHUNKSZ) */
#define MALL    16384         /* all rows (B*S) */
#define NOUT    16777216

// ---- scratch (device globals; no allocations allowed) ----
__device__ __half g_xh [(size_t)NOUT];         // fp16 x (32MB)
__device__ __half g_u0h[(size_t)MALL * FF];    // u0 all chunks (128MB)
__device__ __half g_u2h[(size_t)MALL * FF];    // u2 all chunks (128MB)
__device__ __half g_vh [(size_t)MROWS * FF];   // v, chunk-local (16MB)
__device__ __half g_w0T[(size_t)FF * HH];      // w0^T [n=4096][k=1024]
__device__ __half g_w2T[(size_t)FF * HH];
__device__ __half g_w1T[(size_t)HH * FF];      // w1^T [n=1024][k=4096]
__device__ float g_partial[256];
__device__ float g_D;
__device__ float g_total;

// =================== helpers ===================
__device__ __forceinline__ u32 smem_u32(const void* p) {
    u32 a; asm("{ .reg .u64 t; cvta.to.shared.u64 t, %1; cvt.u32.u64 %0, t; }" : "=r"(a) : "l"(p));
    return a;
}

#define CP16(dst, src) \
    asm volatile("cp.async.cg.shared.global [%0], [%1], 16;" :: "r"(dst), "l"(src) : "memory")
#define CPCOMMIT() asm volatile("cp.async.commit_group;" ::: "memory")
#define CPWAIT1()  asm volatile("cp.async.wait_group 1;" ::: "memory")
#define CPWAIT2()  asm volatile("cp.async.wait_group 2;" ::: "memory")

#define LDSM4(r, addr) \
    asm volatile("ldmatrix.sync.aligned.m8n8.x4.shared.b16 {%0,%1,%2,%3}, [%4];" \
        : "=r"((r)[0]), "=r"((r)[1]), "=r"((r)[2]), "=r"((r)[3]) : "r"(addr))

#define MMA16(d, a, b0_, b1_) \
    asm volatile("mma.sync.aligned.m16n8k16.row.col.f32.f16.f16.f32 " \
        "{%0,%1,%2,%3}, {%4,%5,%6,%7}, {%8,%9}, {%0,%1,%2,%3};" \
        : "+f"((d)[0]), "+f"((d)[1]), "+f"((d)[2]), "+f"((d)[3]) \
        : "r"((a)[0]), "r"((a)[1]), "r"((a)[2]), "r"((a)[3]), "r"(b0_), "r"(b1_))

// rows x 64 k-halves (128B data), row stride 144B -> conflict-free LDSM/STS
#define ROWSTRB  144
#define TILE128  18432   /* 128*144 */
#define TILE64   9216    /*  64*144 */
#define MROWB    2304    /*  16*144 */

// =================== small kernels ===================
__global__ void conv_x_kernel(const float* __restrict__ x) {
    int i = (blockIdx.x * 256 + threadIdx.x) * 4;
    float4 v = *(const float4*)(x + i);
    *(__half2*)(g_xh + i)     = __floats2half2_rn(v.x, v.y);
    *(__half2*)(g_xh + i + 2) = __floats2half2_rn(v.z, v.w);
    if (blockIdx.x == 0 && threadIdx.x == 0) { g_D = 1.0f; g_total = 0.0f; }
}

// 3 transposes in one launch (z selects weight); out[C][R] = half(in[R][C])
__global__ void transpose_all(const float* __restrict__ w0, const float* __restrict__ w1,
                              const float* __restrict__ w2) {
    __shared__ float t[32][33];
    int z = blockIdx.z;
    const float* in; __half* out; int R, C, c0, r0;
    if (z == 0)      { in = w0; out = g_w0T; R = HH; C = FF; c0 = blockIdx.x * 32; r0 = blockIdx.y * 32; }
    else if (z == 1) { in = w2; out = g_w2T; R = HH; C = FF; c0 = blockIdx.x * 32; r0 = blockIdx.y * 32; }
    else             { in = w1; out = g_w1T; R = FF; C = HH; c0 = blockIdx.y * 32; r0 = blockIdx.x * 32; }
    #pragma unroll
    for (int i = 0; i < 32; i += 8)
        t[threadIdx.y + i][threadIdx.x] = in[(size_t)(r0 + threadIdx.y + i) * C + c0 + threadIdx.x];
    __syncthreads();
    #pragma unroll
    for (int i = 0; i < 32; i += 8)
        out[(size_t)(c0 + threadIdx.y + i) * R + r0 + threadIdx.x] = __float2half_rn(t[threadIdx.x][threadIdx.y + i]);
}

// vh[row_local] = silu(D*u0[grow]) * u2[grow], 8 halves/thread
__global__ void silu_mul_kernel(int chunk) {
    const float D = g_D;
    size_t idx = ((size_t)blockIdx.x * 256 + threadIdx.x) * 8;
    int rl  = (int)(idx >> 12);
    int col = (int)(idx & 4095);
    int grow = ((rl >> 9) << 12) + chunk * CHUNKSZ + (rl & 511);
    size_t gi = (size_t)grow * FF + col;
    uint4 a4 = *(const uint4*)(g_u0h + gi);
    uint4 b4 = *(const uint4*)(g_u2h + gi);
    const __half2* a = (const __half2*)&a4;
    const __half2* b = (const __half2*)&b4;
    uint4 o4;
    __half2* o = (__half2*)&o4;
    #pragma unroll
    for (int j = 0; j < 4; j++) {
        float2 af = __half22float2(a[j]);
        float2 bf = __half22float2(b[j]);
        float z0 = D * af.x, z1 = D * af.y;
        float s0 = z0 / (1.0f + __expf(-z0)), s1 = z1 / (1.0f + __expf(-z1));
        o[j] = __floats2half2_rn(s0 * bf.x, s1 * bf.y);
    }
    *(uint4*)(g_vh + (size_t)rl * FF + col) = o4;
}

__global__ void reduce_update_kernel(float* __restrict__ outp, int chunk) {
    __shared__ float red[256];
    int t = threadIdx.x;
    red[t] = g_partial[t];
    __syncthreads();
    for (int s = 128; s > 0; s >>= 1) {
        if (t < s) red[t] += red[t + s];
        __syncthreads();
    }
    if (t == 0) {
        float loss = red[0] * (1.0f / (float)(MROWS * HH));
        float tot = g_total + loss;
        g_total = tot;
        g_D = g_D * (1.0f - 0.001f * loss);
        if (chunk == NCHUNK - 1) outp[NOUT] = tot * (1.0f / (float)NCHUNK);
    }
}

// =================== GEMM1 (per chunk): u{0,2}[chunk rows] = x @ w{0,2}T ===================
// CTA 128x128, 256 thr (8 warps 4m x 2n, warp 32x64), K=1024, k-tile 64, 3 stages, occ 2.
// Chunk c covers global rows {b*4096 + c*512 + [0,512)} for b=0..3.
#define ST1_STAGE (2 * TILE128)    /* 36864 */
#define ST1_BYTES (3 * ST1_STAGE)  /* 110592 */

__device__ __forceinline__ void g1_load(u32 base, const __half* wT, int tid,
                                        int m0, int n0, int kt) {
    #pragma unroll
    for (int i = 0; i < 4; i++) {
        int idx = tid + i * 256;
        int row = idx >> 3, kq = idx & 7;
        CP16(base + (u32)(row * ROWSTRB + kq * 16),
             g_xh + (size_t)(m0 + row) * HH + kt * 64 + kq * 8);
    }
    #pragma unroll
    for (int i = 0; i < 4; i++) {
        int idx = tid + i * 256;
        int row = idx >> 3, kq = idx & 7;
        CP16(base + TILE128 + (u32)(row * ROWSTRB + kq * 16),
             wT + (size_t)(n0 + row) * HH + kt * 64 + kq * 8);
    }
}

__global__ __launch_bounds__(256, 2)
void gemm1_tc(int chunk)
{
    extern __shared__ float smem[];
    const u32 sb = smem_u32(smem);
    const int tid = threadIdx.x, lane = tid & 31, wid = tid >> 5;
    const int wm = wid & 3, wn = wid >> 2;            // 4m x 2n warps, tile 32x64
    // global m0 for this chunk: segment b = y>>2, 128-row block (y&3)
    const int m0 = ((blockIdx.y >> 2) << 12) + chunk * CHUNKSZ + (blockIdx.y & 3) * 128;
    const int n0 = blockIdx.x * 128;
    const int z = blockIdx.z;
    const __half* wT = z ? g_w2T : g_w0T;
    __half* uout = z ? g_u2h : g_u0h;

    float acc[2][8][4];
    #pragma unroll
    for (int a = 0; a < 2; a++)
        #pragma unroll
        for (int b = 0; b < 8; b++)
            #pragma unroll
            for (int c = 0; c < 4; c++) acc[a][b][c] = 0.f;

    const u32 aoff = (u32)((wm * 32 + (lane & 15)) * ROWSTRB) + ((lane >> 4) & 1) * 16;
    const u32 boff = (u32)((wn * 64 + (lane & 15)) * ROWSTRB) + ((lane >> 4) & 1) * 16;

    g1_load(sb, wT, tid, m0, n0, 0); CPCOMMIT();
    g1_load(sb + ST1_STAGE, wT, tid, m0, n0, 1); CPCOMMIT();

    const int KT = HH / 64;  // 16
    for (int kt = 0; kt < KT; ++kt) {
        const u32 base = sb + (u32)(kt % 3) * ST1_STAGE;
        CPWAIT1();
        __syncthreads();
        if (kt + 2 < KT) g1_load(sb + (u32)((kt + 2) % 3) * ST1_STAGE, wT, tid, m0, n0, kt + 2);
        CPCOMMIT();
        #pragma unroll
        for (int ks = 0; ks < 4; ++ks) {
            u32 A[2][4];
            LDSM4(A[0], base + aoff + 0 * MROWB + ks * 32);
            LDSM4(A[1], base + aoff + 1 * MROWB + ks * 32);
            #pragma unroll
            for (int tp = 0; tp < 4; ++tp) {
                u32 b[4];
                LDSM4(b, base + TILE128 + boff + tp * MROWB + ks * 32);
                #pragma unroll
                for (int mt = 0; mt < 2; ++mt) {
                    MMA16(acc[mt][2 * tp],     A[mt], b[0], b[2]);
                    MMA16(acc[mt][2 * tp + 1], A[mt], b[1], b[3]);
                }
            }
        }
    }

    // epilogue: store u as fp16 (global row index)
    const int gq = lane >> 2, tg = lane & 3;
    #pragma unroll
    for (int mt = 0; mt < 2; ++mt) {
        #pragma unroll
        for (int nt = 0; nt < 8; ++nt) {
            const int col = n0 + wn * 64 + nt * 8 + tg * 2;
            #pragma unroll
            for (int h = 0; h < 2; ++h) {
                const int row = m0 + wm * 32 + mt * 16 + gq + h * 8;
                *(__half2*)&uout[(size_t)row * FF + col] =
                    __floats2half2_rn(acc[mt][nt][h * 2], acc[mt][nt][h * 2 + 1]);
            }
        }
    }
}

// =================== GEMM2: out = D^2 * (v @ w1T) + fused loss partials ===================
// CTA 64x128, 256 thr (8 warps 2m x 4n, warp 32x32), K=4096, k-tile 64, 4 stages, occ 2.
#define ST2_STAGE (TILE64 + TILE128)  /* 27648 */
#define ST2_BYTES (4 * ST2_STAGE)     /* 110592 */

__device__ __forceinline__ void g2_load(u32 base, int tid, int m0, int n0, int kt) {
    #pragma unroll
    for (int i = 0; i < 2; i++) {
        int idx = tid + i * 256;
        int row = idx >> 3, kq = idx & 7;
        CP16(base + (u32)(row * ROWSTRB + kq * 16),
             g_vh + (size_t)(m0 + row) * FF + kt * 64 + kq * 8);
    }
    #pragma unroll
    for (int i = 0; i < 4; i++) {
        int idx = tid + i * 256;
        int row = idx >> 3, kq = idx & 7;
        CP16(base + TILE64 + (u32)(row * ROWSTRB + kq * 16),
             g_w1T + (size_t)(n0 + row) * FF + kt * 64 + kq * 8);
    }
}

__global__ __launch_bounds__(256, 2)
void gemm2_tc(const float* __restrict__ x, float* __restrict__ outp, int chunk)
{
    extern __shared__ float smem[];
    const u32 sb = smem_u32(smem);
    const int tid = threadIdx.x, lane = tid & 31, wid = tid >> 5;
    const int wm = wid & 1, wn = wid >> 1;            // 2m x 4n warps, tile 32x32
    const int m0 = blockIdx.y * 64, n0 = blockIdx.x * 128;

    float acc[2][4][4];
    #pragma unroll
    for (int a = 0; a < 2; a++)
        #pragma unroll
        for (int b = 0; b < 4; b++)
            #pragma unroll
            for (int c = 0; c < 4; c++) acc[a][b][c] = 0.f;

    const u32 aoff = (u32)((wm * 32 + (lane & 15)) * ROWSTRB) + ((lane >> 4) & 1) * 16;
    const u32 boff = (u32)((wn * 32 + (lane & 15)) * ROWSTRB) + ((lane >> 4) & 1) * 16;

    g2_load(sb, tid, m0, n0, 0); CPCOMMIT();
    g2_load(sb + ST2_STAGE, tid, m0, n0, 1); CPCOMMIT();
    g2_load(sb + 2 * ST2_STAGE, tid, m0, n0, 2); CPCOMMIT();

    const int KT = FF / 64;  // 64
    for (int kt = 0; kt < KT; ++kt) {
        const u32 base = sb + (u32)(kt & 3) * ST2_STAGE;
        CPWAIT2();
        __syncthreads();
        if (kt + 3 < KT) g2_load(sb + (u32)((kt + 3) & 3) * ST2_STAGE, tid, m0, n0, kt + 3);
        CPCOMMIT();
        #pragma unroll
        for (int ks = 0; ks < 4; ++ks) {
            u32 A[2][4], b0[4], b1[4];
            LDSM4(A[0], base + aoff + 0 * MROWB + ks * 32);
            LDSM4(A[1], base + aoff + 1 * MROWB + ks * 32);
            LDSM4(b0, base + TILE64 + boff + 0 * MROWB + ks * 32);
            LDSM4(b1, base + TILE64 + boff + 1 * MROWB + ks * 32);
            #pragma unroll
            for (int mt = 0; mt < 2; ++mt) {
                MMA16(acc[mt][0], A[mt], b0[0], b0[2]);
                MMA16(acc[mt][1], A[mt], b0[1], b0[3]);
                MMA16(acc[mt][2], A[mt], b1[0], b1[2]);
                MMA16(acc[mt][3], A[mt], b1[1], b1[3]);
            }
        }
    }

    // epilogue: out = D^2*acc, fused (out - x)^2 partial
    const float D = g_D, D2 = D * D;
    const int gq = lane >> 2, tg = lane & 3;
    float sq = 0.0f;
    #pragma unroll
    for (int mt = 0; mt < 2; ++mt) {
        #pragma unroll
        for (int nt = 0; nt < 4; ++nt) {
            const int col = n0 + wn * 32 + nt * 8 + tg * 2;
            #pragma unroll
            for (int h = 0; h < 2; ++h) {
                const int lm = m0 + wm * 32 + mt * 16 + gq + h * 8;
                const int g = ((lm >> 9) << 12) + chunk * CHUNKSZ + (lm & 511);
                float2 xv = *(const float2*)(x + (size_t)g * HH + col);
                float2 ov;
                ov.x = D2 * acc[mt][nt][h * 2];
                ov.y = D2 * acc[mt][nt][h * 2 + 1];
                *(float2*)(outp + (size_t)g * HH + col) = ov;
                float d0 = ov.x - xv.x, d1 = ov.y - xv.y;
                sq += d0 * d0 + d1 * d1;
            }
        }
    }
    #pragma unroll
    for (int off = 16; off > 0; off >>= 1)
        sq += __shfl_xor_sync(0xFFFFFFFFu, sq, off);
    __syncthreads();
    float* red = smem;
    if (lane == 0) red[wid] = sq;
    __syncthreads();
    if (tid == 0) {
        float s = 0.f;
        #pragma unroll
        for (int i = 0; i < 8; i++) s += red[i];
        g_partial[blockIdx.y * 8 + blockIdx.x] = s;
    }
}

// =================== host ===================
extern "C" void kernel_launch(void* const* d_in, const int* in_sizes, int n_in,
                              void* d_out, int out_size)
{
    const float* x  = (const float*)d_in[0];
    const float* w0 = (const float*)d_in[1];
    const float* w1 = (const float*)d_in[2];
    const float* w2 = (const float*)d_in[3];
    float* out = (float*)d_out;

    // Streams/events created once on the eager correctness call (no capture active),
    // reused during graph capture (fork/join via events = standard capture pattern).
    static cudaStream_t sS = nullptr;
    static cudaEvent_t evF = nullptr, e1[NCHUNK];
    if (!sS) {
        cudaStreamCreateWithFlags(&sS, cudaStreamNonBlocking);
        cudaEventCreateWithFlags(&evF, cudaEventDisableTiming);
        for (int c = 0; c < NCHUNK; ++c)
            cudaEventCreateWithFlags(&e1[c], cudaEventDisableTiming);
        cudaFuncSetAttribute(gemm1_tc, cudaFuncAttributeMaxDynamicSharedMemorySize, ST1_BYTES);
        cudaFuncSetAttribute(gemm2_tc, cudaFuncAttributeMaxDynamicSharedMemorySize, ST2_BYTES);
    }

    conv_x_kernel<<<NOUT / 1024, 256>>>(x);
    transpose_all<<<dim3(128, 32, 3), dim3(32, 8)>>>(w0, w1, w2);

    // chunk 0's u0/u2 on the main stream (needed first)
    gemm1_tc<<<dim3(32, 16, 2), 256, ST1_BYTES>>>(0);

    // fork: side stream computes gemm1 for chunks 1..7 concurrently with the chain
    cudaEventRecord(evF, 0);
    cudaStreamWaitEvent(sS, evF, 0);
    for (int c = 1; c < NCHUNK; ++c) {
        gemm1_tc<<<dim3(32, 16, 2), 256, ST1_BYTES, sS>>>(c);
        cudaEventRecord(e1[c], sS);
    }

    // serial D-recurrence chain on the main stream; chain(c) gated on gemm1(c)
    for (int c = 0; c < NCHUNK; ++c) {
        if (c > 0) cudaStreamWaitEvent(0, e1[c], 0);   // also joins side stream by c=7
        silu_mul_kernel<<<(MROWS * FF) / 2048, 256>>>(c);
        gemm2_tc<<<dim3(8, 32), 256, ST2_BYTES>>>(x, out, c);
        reduce_update_kernel<<<1, 256>>>(out, c);
    }
}